// round 9
// baseline (speedup 1.0000x reference)
#include <cuda_runtime.h>
#include <cuda_bf16.h>
#include <cuda_fp8.h>
#include <cstdint>

// ---------------- problem constants ----------------
#define N_FEAT   131072
#define DIM      128
#define K_CENT   1024
#define M_TILE   128
#define N_CHUNK  64
#define N_CHUNKS (K_CENT / N_CHUNK)       // 16
#define N_CTAS   (N_FEAT / M_TILE)        // 1024

// ---------------- SMEM map ----------------
#define SM_A8    0u                        // 16 KB: 128 x 128B fp8 features (SW128)
#define SM_ABF   16384u                    // 32 KB: 128 x 256B bf16 features (chunk^row swizzle)
#define SM_B     49152u                    // 3 x 8 KB fp8 center buffers (SW128)
#define SMEM_BYTES 73728u

// ---------------- device scratch ----------------
__device__ __align__(128) uint8_t g_c8[K_CENT * DIM];   // normalized centers, e4m3
__device__ float g_partial[N_CTAS];

// ---------------- helpers ----------------
__device__ __forceinline__ unsigned pack_bf16x2(float lo, float hi) {
    __nv_bfloat162 p = __floats2bfloat162_rn(lo, hi);
    return *reinterpret_cast<unsigned*>(&p);
}

// 4 floats -> 4 e4m3 bytes (byte i = element i)
__device__ __forceinline__ uint32_t pack_e4m3x4(float f0, float f1, float f2, float f3) {
    uint16_t lo, hi;
    asm("cvt.rn.satfinite.e4m3x2.f32 %0, %1, %2;" : "=h"(lo) : "f"(f1), "f"(f0));
    asm("cvt.rn.satfinite.e4m3x2.f32 %0, %1, %2;" : "=h"(hi) : "f"(f3), "f"(f2));
    return (uint32_t)lo | ((uint32_t)hi << 16);
}

__device__ __forceinline__ void ldm_x4(uint32_t& r0, uint32_t& r1, uint32_t& r2,
                                       uint32_t& r3, uint32_t addr) {
    asm volatile("ldmatrix.sync.aligned.m8n8.x4.shared.b16 {%0,%1,%2,%3}, [%4];\n"
                 : "=r"(r0), "=r"(r1), "=r"(r2), "=r"(r3)
                 : "r"(addr));
}

__device__ __forceinline__ void mma_fp8(float* c,
                                        uint32_t a0, uint32_t a1, uint32_t a2, uint32_t a3,
                                        uint32_t b0, uint32_t b1) {
    asm volatile("mma.sync.aligned.m16n8k32.row.col.f32.e4m3.e4m3.f32 "
                 "{%0,%1,%2,%3}, {%4,%5,%6,%7}, {%8,%9}, {%0,%1,%2,%3};\n"
                 : "+f"(c[0]), "+f"(c[1]), "+f"(c[2]), "+f"(c[3])
                 : "r"(a0), "r"(a1), "r"(a2), "r"(a3), "r"(b0), "r"(b1));
}

__device__ __forceinline__ void cp16(uint32_t dst, const void* src) {
    asm volatile("cp.async.cg.shared.global [%0], [%1], 16;\n" :: "r"(dst), "l"(src));
}
#define CP_COMMIT() asm volatile("cp.async.commit_group;\n" ::: "memory")
#define CP_WAIT2()  asm volatile("cp.async.wait_group 2;\n" ::: "memory")

// ---------------- kernel 1: normalize centers -> e4m3 ----------------
__global__ void prep_centers(const float* __restrict__ C) {
    int k = blockIdx.x;
    int t = threadIdx.x;          // 0..127
    float v = C[(size_t)k * DIM + t];
    float ss = v * v;
    #pragma unroll
    for (int off = 16; off; off >>= 1) ss += __shfl_xor_sync(0xffffffffu, ss, off);
    __shared__ float s4[4];
    if ((t & 31) == 0) s4[t >> 5] = ss;
    __syncthreads();
    float tot = s4[0] + s4[1] + s4[2] + s4[3];
    float inv = 1.0f / fmaxf(sqrtf(tot), 1e-12f);
    uint16_t b;
    float z = 0.0f;
    asm("cvt.rn.satfinite.e4m3x2.f32 %0, %1, %2;" : "=h"(b) : "f"(z), "f"(v * inv));
    g_c8[(size_t)k * DIM + t] = (uint8_t)(b & 0xFF);
}

// ---------------- kernel 2: fp8 fused GEMM + argmax + exact loss ----------------
// Warp w: M rows [32*(w&3), +32) x N cols [32*(w>>2), +32) of each 64-center chunk.
// A8/B: 128B rows, 16B chunk c stored at (c ^ (r&7)).  ABF: 256B rows, same xor.
__global__ void __launch_bounds__(256)
cluster_main(const float* __restrict__ F, const float* __restrict__ Craw) {
    extern __shared__ unsigned char smem_raw[];
    const uint32_t smem_u32 = (uint32_t)__cvta_generic_to_shared(smem_raw);

    const int t    = threadIdx.x;
    const int lane = t & 31;
    const int warp = t >> 5;
    const int mrow_base = (warp & 3) * 32;
    const int nh        = warp >> 2;
    const int m0   = blockIdx.x * M_TILE;

    // ---- B staging addressing: thread -> (center row, 2x16B chunks) ----
    const int bn = t >> 2;                      // 0..63
    const int bc = (t & 3) * 2;                 // chunk base 0,2,4,6
    uint32_t bdst[2];
    #pragma unroll
    for (int i = 0; i < 2; i++)
        bdst[i] = (uint32_t)(bn * 128 + (((bc + i) ^ (bn & 7)) * 16));
    const uint8_t* bsrc0 = g_c8 + (size_t)bn * DIM + bc * 16;

    // ---- prefetch B chunk 0 ----
    #pragma unroll
    for (int i = 0; i < 2; i++)
        cp16(smem_u32 + SM_B + bdst[i], bsrc0 + i * 16);
    CP_COMMIT();

    // ---- load + normalize features -> fp8 (A8) + bf16 (ABF) SMEM ----
    {
        int r = t >> 1;                    // feature row (2 threads/row)
        int h = t & 1;                     // which 64-float half
        const float4* gp =
            reinterpret_cast<const float4*>(F + (size_t)(m0 + r) * DIM + h * 64);
        float ss = 0.f;
        #pragma unroll
        for (int i = 0; i < 16; i++) {
            float4 a = gp[i];
            ss += a.x * a.x + a.y * a.y + a.z * a.z + a.w * a.w;
        }
        ss += __shfl_xor_sync(0xffffffffu, ss, 1);
        float inv = 1.0f / fmaxf(sqrtf(ss), 1e-12f);
        #pragma unroll
        for (int i = 0; i < 4; i++) {
            float4 v0 = gp[4 * i], v1 = gp[4 * i + 1];
            float4 v2 = gp[4 * i + 2], v3 = gp[4 * i + 3];
            v0.x *= inv; v0.y *= inv; v0.z *= inv; v0.w *= inv;
            v1.x *= inv; v1.y *= inv; v1.z *= inv; v1.w *= inv;
            v2.x *= inv; v2.y *= inv; v2.z *= inv; v2.w *= inv;
            v3.x *= inv; v3.y *= inv; v3.z *= inv; v3.w *= inv;
            // fp8 chunk (16 bytes = 16 k-values)
            uint4 p8;
            p8.x = pack_e4m3x4(v0.x, v0.y, v0.z, v0.w);
            p8.y = pack_e4m3x4(v1.x, v1.y, v1.z, v1.w);
            p8.z = pack_e4m3x4(v2.x, v2.y, v2.z, v2.w);
            p8.w = pack_e4m3x4(v3.x, v3.y, v3.z, v3.w);
            int c8 = h * 4 + i;
            *reinterpret_cast<uint4*>(smem_raw + SM_A8 +
                (uint32_t)(r * 128 + ((c8 ^ (r & 7)) * 16))) = p8;
            // bf16 chunks (two 16B chunks = 8+8 k-values)
            uint4 q0, q1;
            q0.x = pack_bf16x2(v0.x, v0.y); q0.y = pack_bf16x2(v0.z, v0.w);
            q0.z = pack_bf16x2(v1.x, v1.y); q0.w = pack_bf16x2(v1.z, v1.w);
            q1.x = pack_bf16x2(v2.x, v2.y); q1.y = pack_bf16x2(v2.z, v2.w);
            q1.z = pack_bf16x2(v3.x, v3.y); q1.w = pack_bf16x2(v3.z, v3.w);
            int cb = h * 8 + 2 * i;
            *reinterpret_cast<uint4*>(smem_raw + SM_ABF +
                (uint32_t)(r * 256 + ((cb ^ (r & 7)) * 16))) = q0;
            *reinterpret_cast<uint4*>(smem_raw + SM_ABF +
                (uint32_t)(r * 256 + (((cb + 1) ^ (r & 7)) * 16))) = q1;
        }
    }
    __syncthreads();

    // ---- register all A fragments: 2 m-tiles x 4 k32-steps x 4 regs ----
    const int sub = lane >> 3, li = lane & 7;
    const int a_cadd = sub >> 1;               // +1 chunk for k upper 16B
    uint32_t af[2][4][4];
    #pragma unroll
    for (int mi = 0; mi < 2; mi++) {
        int a_row = mrow_base + 16 * mi + ((sub & 1) << 3) + li;
        uint32_t ra = smem_u32 + SM_A8 + a_row * 128;
        int r7 = a_row & 7;
        #pragma unroll
        for (int ks = 0; ks < 4; ks++)
            ldm_x4(af[mi][ks][0], af[mi][ks][1], af[mi][ks][2], af[mi][ks][3],
                   ra + ((((ks << 1) + a_cadd) ^ r7) << 4));
    }

    // ---- prefetch B chunks 1, 2 ----
    #pragma unroll
    for (int i = 0; i < 2; i++)
        cp16(smem_u32 + SM_B + 8192u + bdst[i], bsrc0 + (size_t)1 * N_CHUNK * DIM + i * 16);
    CP_COMMIT();
    #pragma unroll
    for (int i = 0; i < 2; i++)
        cp16(smem_u32 + SM_B + 16384u + bdst[i], bsrc0 + (size_t)2 * N_CHUNK * DIM + i * 16);
    CP_COMMIT();

    // ---- B ldmatrix addressing (this warp's 32-col half: 2 groups of 16 rows) ----
    const int b_ck = sub & 1;                   // k 16B-half select
    uint32_t b_off[2];
    int      b_r7[2];
    #pragma unroll
    for (int jj = 0; jj < 2; jj++) {
        int nr = 32 * nh + 16 * jj + ((sub >> 1) << 3) + li;
        b_off[jj] = (uint32_t)(nr * 128);
        b_r7[jj]  = nr & 7;
    }

    float bestv[2][2] = {{-3.0e38f, -3.0e38f}, {-3.0e38f, -3.0e38f}};
    int   besti[2][2] = {{0, 0}, {0, 0}};

    // ---- main loop: 16 chunks, 3-stage cp.async pipeline ----
    for (int ch = 0; ch < N_CHUNKS; ch++) {
        CP_WAIT2();
        __syncthreads();
        const uint32_t bb = smem_u32 + SM_B + (uint32_t)(ch % 3) * 8192u;

        float acc[2][4][4] = {};
        #pragma unroll
        for (int ks = 0; ks < 4; ks++) {
            #pragma unroll
            for (int jj = 0; jj < 2; jj++) {
                uint32_t b0, b1, b2, b3;
                ldm_x4(b0, b1, b2, b3,
                       bb + b_off[jj] + ((((ks << 1) + b_ck) ^ b_r7[jj]) << 4));
                mma_fp8(acc[0][2 * jj],     af[0][ks][0], af[0][ks][1], af[0][ks][2], af[0][ks][3], b0, b1);
                mma_fp8(acc[0][2 * jj + 1], af[0][ks][0], af[0][ks][1], af[0][ks][2], af[0][ks][3], b2, b3);
                mma_fp8(acc[1][2 * jj],     af[1][ks][0], af[1][ks][1], af[1][ks][2], af[1][ks][3], b0, b1);
                mma_fp8(acc[1][2 * jj + 1], af[1][ks][0], af[1][ks][1], af[1][ks][2], af[1][ks][3], b2, b3);
            }
        }

        // running argmax over this chunk's 32 cols (per m-row pair)
        {
            int cb = ch * N_CHUNK + 32 * nh + (lane & 3) * 2;
            #pragma unroll
            for (int mi = 0; mi < 2; mi++) {
                #pragma unroll
                for (int nt = 0; nt < 4; nt++) {
                    int ci = cb + 8 * nt;
                    float* a4 = acc[mi][nt];
                    if (a4[0] > bestv[mi][0]) { bestv[mi][0] = a4[0]; besti[mi][0] = ci;     }
                    if (a4[1] > bestv[mi][0]) { bestv[mi][0] = a4[1]; besti[mi][0] = ci + 1; }
                    if (a4[2] > bestv[mi][1]) { bestv[mi][1] = a4[2]; besti[mi][1] = ci;     }
                    if (a4[3] > bestv[mi][1]) { bestv[mi][1] = a4[3]; besti[mi][1] = ci + 1; }
                }
            }
        }
        __syncthreads();

        if (ch + 3 < N_CHUNKS) {
            const uint8_t* s = bsrc0 + (size_t)(ch + 3) * N_CHUNK * DIM;
            uint32_t dstbase = smem_u32 + SM_B + (uint32_t)(ch % 3) * 8192u;
            #pragma unroll
            for (int i = 0; i < 2; i++) cp16(dstbase + bdst[i], s + i * 16);
        }
        CP_COMMIT();
    }

    // ---- quad reduce argmax (4 lanes per row) ----
    #pragma unroll
    for (int off = 1; off <= 2; off <<= 1) {
        #pragma unroll
        for (int mi = 0; mi < 2; mi++) {
            #pragma unroll
            for (int h = 0; h < 2; h++) {
                float ov = __shfl_xor_sync(0xffffffffu, bestv[mi][h], off);
                int   oi = __shfl_xor_sync(0xffffffffu, besti[mi][h], off);
                if (ov > bestv[mi][h] || (ov == bestv[mi][h] && oi < besti[mi][h])) {
                    bestv[mi][h] = ov; besti[mi][h] = oi;
                }
            }
        }
    }

    // ---- combine two N-half warps per row (A8 region is dead; reuse it) ----
    float* bv = reinterpret_cast<float*>(smem_raw);           // [2][128]
    int*   bi = reinterpret_cast<int*>(smem_raw + 1024);      // [2][128]
    if ((lane & 3) == 0) {
        int r0 = mrow_base + (lane >> 2);
        #pragma unroll
        for (int mi = 0; mi < 2; mi++) {
            #pragma unroll
            for (int h = 0; h < 2; h++) {
                int row = r0 + 16 * mi + 8 * h;
                bv[nh * 128 + row] = bestv[mi][h];
                bi[nh * 128 + row] = besti[mi][h];
            }
        }
    }
    __syncthreads();

    // ---- exact per-row loss: sum (f_bf16 - C_fp32)^2, C read from L2 ----
    float* lr = reinterpret_cast<float*>(smem_raw + 2048);    // [128]
    if (t < 128) {
        float v0 = bv[t], v1 = bv[128 + t];
        int   i0 = bi[t], i1 = bi[128 + t];
        int idx = (v0 > v1 || (v0 == v1 && i0 < i1)) ? i0 : i1;
        const float4* cp = reinterpret_cast<const float4*>(Craw + (size_t)idx * DIM);
        float lsum = 0.f;
        #pragma unroll
        for (int j = 0; j < 16; j++) {
            uint4 fb = *reinterpret_cast<const uint4*>(
                smem_raw + SM_ABF + (uint32_t)(t * 256 + ((j ^ (t & 7)) * 16)));
            float4 c0 = cp[2 * j], c1 = cp[2 * j + 1];
            float f0 = __int_as_float(fb.x << 16);
            float f1 = __int_as_float(fb.x & 0xFFFF0000u);
            float f2 = __int_as_float(fb.y << 16);
            float f3 = __int_as_float(fb.y & 0xFFFF0000u);
            float f4 = __int_as_float(fb.z << 16);
            float f5 = __int_as_float(fb.z & 0xFFFF0000u);
            float f6 = __int_as_float(fb.w << 16);
            float f7 = __int_as_float(fb.w & 0xFFFF0000u);
            float d;
            d = f0 - c0.x; lsum += d * d;
            d = f1 - c0.y; lsum += d * d;
            d = f2 - c0.z; lsum += d * d;
            d = f3 - c0.w; lsum += d * d;
            d = f4 - c1.x; lsum += d * d;
            d = f5 - c1.y; lsum += d * d;
            d = f6 - c1.z; lsum += d * d;
            d = f7 - c1.w; lsum += d * d;
        }
        lr[t] = lsum;
    }
    __syncthreads();
    #pragma unroll
    for (int off = 64; off; off >>= 1) {
        if (t < off) lr[t] += lr[t + off];
        __syncthreads();
    }
    if (t == 0) g_partial[blockIdx.x] = lr[0];
}

// ---------------- kernel 3: deterministic final reduce ----------------
__global__ void finalize_loss(float* __restrict__ out) {
    __shared__ float sh[256];
    int t = threadIdx.x;
    float s = g_partial[t] + g_partial[t + 256] + g_partial[t + 512] + g_partial[t + 768];
    sh[t] = s;
    __syncthreads();
    #pragma unroll
    for (int off = 128; off; off >>= 1) {
        if (t < off) sh[t] += sh[t + off];
        __syncthreads();
    }
    if (t == 0) out[0] = sh[0] / (float)N_FEAT;
}

// ---------------- launch ----------------
extern "C" void kernel_launch(void* const* d_in, const int* in_sizes, int n_in,
                              void* d_out, int out_size) {
    const float* features = (const float*)d_in[0];
    const float* centers  = (const float*)d_in[1];
    if (n_in >= 2 && in_sizes[0] < in_sizes[1]) {   // defensive: order by size
        const float* tmp = features; features = centers; centers = tmp;
    }
    cudaFuncSetAttribute(cluster_main,
                         cudaFuncAttributeMaxDynamicSharedMemorySize, SMEM_BYTES);
    prep_centers<<<K_CENT, DIM>>>(centers);
    cluster_main<<<N_CTAS, 256, SMEM_BYTES>>>(features, centers);
    finalize_loss<<<1, 256>>>((float*)d_out);
}

// round 10
// speedup vs baseline: 1.2023x; 1.2023x over previous
#include <cuda_runtime.h>
#include <cuda_bf16.h>
#include <cstdint>

// ---------------- problem constants ----------------
#define N_FEAT   131072
#define DIM      128
#define K_CENT   1024
#define M_TILE   128
#define N_CHUNK  64
#define N_CHUNKS (K_CENT / N_CHUNK)       // 16
#define N_CTAS   (N_FEAT / M_TILE)        // 1024

// ---------------- SMEM map ----------------
// [0, 32768)       A tile: 128 rows x 256B bf16, chunk^row swizzle
// [32768, 98304)   B ring: 4 buffers x 16 KB (64 rows x 256B each)
#define SM_B       32768u
#define SMEM_BYTES 98304u

// ---------------- device scratch ----------------
__device__ __nv_bfloat16 g_cbf[K_CENT * DIM];  // normalized centers, bf16
__device__ float         g_cn1[K_CENT];         // ||C_k||
__device__ float         g_cn2[K_CENT];         // ||C_k||^2
__device__ float         g_partial[N_CTAS];     // per-CTA loss partials
__device__ unsigned int  g_ticket;              // last-CTA ticket (zero-init, self-reset)

// ---------------- helpers ----------------
__device__ __forceinline__ unsigned pack_bf16x2(float lo, float hi) {
    __nv_bfloat162 p = __floats2bfloat162_rn(lo, hi);
    return *reinterpret_cast<unsigned*>(&p);
}

__device__ __forceinline__ void ldm_x4(uint32_t& r0, uint32_t& r1, uint32_t& r2,
                                       uint32_t& r3, uint32_t addr) {
    asm volatile("ldmatrix.sync.aligned.m8n8.x4.shared.b16 {%0,%1,%2,%3}, [%4];\n"
                 : "=r"(r0), "=r"(r1), "=r"(r2), "=r"(r3)
                 : "r"(addr));
}

__device__ __forceinline__ void mma_bf16(float* c,
                                         uint32_t a0, uint32_t a1, uint32_t a2, uint32_t a3,
                                         uint32_t b0, uint32_t b1) {
    asm volatile("mma.sync.aligned.m16n8k16.row.col.f32.bf16.bf16.f32 "
                 "{%0,%1,%2,%3}, {%4,%5,%6,%7}, {%8,%9}, {%0,%1,%2,%3};\n"
                 : "+f"(c[0]), "+f"(c[1]), "+f"(c[2]), "+f"(c[3])
                 : "r"(a0), "r"(a1), "r"(a2), "r"(a3), "r"(b0), "r"(b1));
}

__device__ __forceinline__ void cp16(uint32_t dst, const void* src) {
    asm volatile("cp.async.cg.shared.global [%0], [%1], 16;\n" :: "r"(dst), "l"(src));
}
#define CP_COMMIT() asm volatile("cp.async.commit_group;\n" ::: "memory")
#define CP_WAIT2()  asm volatile("cp.async.wait_group 2;\n" ::: "memory")

// ---------------- kernel 1: normalize centers (warp per center) ----------------
__global__ void prep_centers(const float* __restrict__ C) {
    int w    = threadIdx.x >> 5;
    int lane = threadIdx.x & 31;
    int k    = blockIdx.x * 8 + w;
    const float4* row = reinterpret_cast<const float4*>(C + (size_t)k * DIM);
    float4 v = row[lane];
    float ss = v.x * v.x + v.y * v.y + v.z * v.z + v.w * v.w;
    #pragma unroll
    for (int off = 16; off; off >>= 1) ss += __shfl_xor_sync(0xffffffffu, ss, off);
    float norm = sqrtf(ss);
    float inv  = 1.0f / fmaxf(norm, 1e-12f);
    uint2 o;
    o.x = pack_bf16x2(v.x * inv, v.y * inv);
    o.y = pack_bf16x2(v.z * inv, v.w * inv);
    *reinterpret_cast<uint2*>(
        reinterpret_cast<unsigned char*>(g_cbf) + (size_t)k * 256 + lane * 8) = o;
    if (lane == 0) { g_cn1[k] = norm; g_cn2[k] = ss; }
}

// ---------------- kernel 2: fused GEMM + argmax + loss + final reduce ----------------
// Warp w: M rows [32*(w&3), +32) x N cols [32*(w>>2), +32) of each 64-center chunk.
// Swizzle everywhere: 16B chunk c of row r stored at chunk (c ^ (r & 7)); rows 256B.
__global__ void __launch_bounds__(256, 2)
cluster_main(const float* __restrict__ F, float* __restrict__ out) {
    extern __shared__ unsigned char smem_raw[];
    const uint32_t smem_u32 = (uint32_t)__cvta_generic_to_shared(smem_raw);

    const int t    = threadIdx.x;
    const int lane = t & 31;
    const int warp = t >> 5;
    const int mrow_base = (warp & 3) * 32;
    const int nh        = warp >> 2;
    const int m0   = blockIdx.x * M_TILE;

    // ---- B staging addressing (thread: one center row quarter, 4 x 16B) ----
    const int bn = t >> 2;                      // center row in chunk 0..63
    const int bq = t & 3;                       // quarter of the 256B row
    uint32_t bdst[4];
    #pragma unroll
    for (int i = 0; i < 4; i++) {
        int c = bq * 4 + i;
        bdst[i] = (uint32_t)(bn * 256 + ((c ^ (bn & 7)) * 16));
    }
    const __nv_bfloat16* bsrc0 = g_cbf + (size_t)bn * DIM + bq * 32;

    // ---- prefetch B chunks 0,1,2 into ring buffers 0,1,2 ----
    #pragma unroll
    for (int n = 0; n < 3; n++) {
        uint32_t db = smem_u32 + SM_B + (uint32_t)n * 16384u;
        const __nv_bfloat16* s = bsrc0 + (size_t)n * N_CHUNK * DIM;
        #pragma unroll
        for (int i = 0; i < 4; i++) cp16(db + bdst[i], s + i * 8);
        CP_COMMIT();
    }

    // ---- load + normalize features into swizzled bf16 A SMEM [0, 32768) ----
    {
        int r = t >> 1;
        int h = t & 1;
        const float4* gp =
            reinterpret_cast<const float4*>(F + (size_t)(m0 + r) * DIM + h * 64);
        float ss = 0.f;
        #pragma unroll
        for (int i = 0; i < 16; i++) {
            float4 a = gp[i];
            ss += a.x * a.x + a.y * a.y + a.z * a.z + a.w * a.w;
        }
        ss += __shfl_xor_sync(0xffffffffu, ss, 1);   // partner lane = same row
        float inv = 1.0f / fmaxf(sqrtf(ss), 1e-12f);
        #pragma unroll
        for (int i = 0; i < 8; i++) {
            float4 a = gp[2 * i];
            float4 b = gp[2 * i + 1];
            uint4 val;
            val.x = pack_bf16x2(a.x * inv, a.y * inv);
            val.y = pack_bf16x2(a.z * inv, a.w * inv);
            val.z = pack_bf16x2(b.x * inv, b.y * inv);
            val.w = pack_bf16x2(b.z * inv, b.w * inv);
            int c = h * 8 + i;
            *reinterpret_cast<uint4*>(smem_raw + r * 256 + ((c ^ (r & 7)) * 16)) = val;
        }
    }
    __syncthreads();

    // ---- register all A fragments (2 m-tiles x 8 k-steps x 4 regs) ----
    const int sub = lane >> 3, li = lane & 7;
    uint32_t af[2][8][4];
    #pragma unroll
    for (int mi = 0; mi < 2; mi++) {
        int a_row = mrow_base + 16 * mi + ((sub & 1) << 3) + li;
        uint32_t ra = smem_u32 + a_row * 256;
        int r7 = a_row & 7;
        int cadd = sub >> 1;
        #pragma unroll
        for (int ks = 0; ks < 8; ks++)
            ldm_x4(af[mi][ks][0], af[mi][ks][1], af[mi][ks][2], af[mi][ks][3],
                   ra + ((((ks << 1) + cadd) ^ r7) << 4));
    }

    // ---- B ldmatrix addressing (this warp's 32-col half: 2 groups of 16 rows) ----
    const int b_ck = sub & 1;
    uint32_t b_off[2];
    int      b_r7[2];
    #pragma unroll
    for (int jj = 0; jj < 2; jj++) {
        int nr = 32 * nh + 16 * jj + ((sub >> 1) << 3) + li;
        b_off[2 - 2] = b_off[0];  // no-op to appease unroll; real assign below
        b_off[jj] = (uint32_t)(nr * 256);
        b_r7[jj]  = nr & 7;
    }

    float bestv[2][2] = {{-3.0e38f, -3.0e38f}, {-3.0e38f, -3.0e38f}};
    int   besti[2][2] = {{0, 0}, {0, 0}};

    // ---- main loop: 16 chunks, 4-buffer ring, prefetch distance 3, ONE sync/iter ----
    for (int ch = 0; ch < N_CHUNKS; ch++) {
        CP_WAIT2();
        __syncthreads();     // chunk ch ready for everyone; iter ch-1 fully consumed

        // prefetch ch+3 into buffer (ch+3)&3 (== consumed at iter ch-1 -> safe)
        if (ch + 3 < N_CHUNKS) {
            uint32_t db = smem_u32 + SM_B + (uint32_t)((ch + 3) & 3) * 16384u;
            const __nv_bfloat16* s = bsrc0 + (size_t)(ch + 3) * N_CHUNK * DIM;
            #pragma unroll
            for (int i = 0; i < 4; i++) cp16(db + bdst[i], s + i * 8);
        }
        CP_COMMIT();         // always: keeps wait_group(2) accounting uniform

        const uint32_t bb = smem_u32 + SM_B + (uint32_t)(ch & 3) * 16384u;
        float acc[2][4][4] = {};
        #pragma unroll
        for (int ks = 0; ks < 8; ks++) {
            #pragma unroll
            for (int jj = 0; jj < 2; jj++) {
                uint32_t b0, b1, b2, b3;
                ldm_x4(b0, b1, b2, b3,
                       bb + b_off[jj] + ((((ks << 1) + b_ck) ^ b_r7[jj]) << 4));
                mma_bf16(acc[0][2 * jj],     af[0][ks][0], af[0][ks][1], af[0][ks][2], af[0][ks][3], b0, b1);
                mma_bf16(acc[0][2 * jj + 1], af[0][ks][0], af[0][ks][1], af[0][ks][2], af[0][ks][3], b2, b3);
                mma_bf16(acc[1][2 * jj],     af[1][ks][0], af[1][ks][1], af[1][ks][2], af[1][ks][3], b0, b1);
                mma_bf16(acc[1][2 * jj + 1], af[1][ks][0], af[1][ks][1], af[1][ks][2], af[1][ks][3], b2, b3);
            }
        }

        // running argmax over this chunk's 32 cols
        int cb = ch * N_CHUNK + 32 * nh + (lane & 3) * 2;
        #pragma unroll
        for (int mi = 0; mi < 2; mi++) {
            #pragma unroll
            for (int nt = 0; nt < 4; nt++) {
                int ci = cb + 8 * nt;
                float* a4 = acc[mi][nt];
                if (a4[0] > bestv[mi][0]) { bestv[mi][0] = a4[0]; besti[mi][0] = ci;     }
                if (a4[1] > bestv[mi][0]) { bestv[mi][0] = a4[1]; besti[mi][0] = ci + 1; }
                if (a4[2] > bestv[mi][1]) { bestv[mi][1] = a4[2]; besti[mi][1] = ci;     }
                if (a4[3] > bestv[mi][1]) { bestv[mi][1] = a4[3]; besti[mi][1] = ci + 1; }
            }
        }
    }

    // ---- quad reduce argmax across the 4 lanes sharing each row ----
    #pragma unroll
    for (int off = 1; off <= 2; off <<= 1) {
        #pragma unroll
        for (int mi = 0; mi < 2; mi++) {
            #pragma unroll
            for (int h = 0; h < 2; h++) {
                float ov = __shfl_xor_sync(0xffffffffu, bestv[mi][h], off);
                int   oi = __shfl_xor_sync(0xffffffffu, besti[mi][h], off);
                if (ov > bestv[mi][h] || (ov == bestv[mi][h] && oi < besti[mi][h])) {
                    bestv[mi][h] = ov; besti[mi][h] = oi;
                }
            }
        }
    }

    // ---- combine the two N-half warps per row (A region is dead; reuse) ----
    __syncthreads();
    float* bv = reinterpret_cast<float*>(smem_raw);           // [2][128]
    int*   bi = reinterpret_cast<int*>(smem_raw + 1024);      // [2][128]
    if ((lane & 3) == 0) {
        int r0 = mrow_base + (lane >> 2);
        #pragma unroll
        for (int mi = 0; mi < 2; mi++) {
            #pragma unroll
            for (int h = 0; h < 2; h++) {
                int row = r0 + 16 * mi + 8 * h;
                bv[nh * 128 + row] = bestv[mi][h];
                bi[nh * 128 + row] = besti[mi][h];
            }
        }
    }
    __syncthreads();

    float* lr = reinterpret_cast<float*>(smem_raw + 2048);    // [128]
    if (t < 128) {
        float v0 = bv[t], v1 = bv[128 + t];
        int   i0 = bi[t], i1 = bi[128 + t];
        float v; int i;
        if (v0 > v1 || (v0 == v1 && i0 < i1)) { v = v0; i = i0; } else { v = v1; i = i1; }
        // loss row = 1 - 2 * sim * ||C|| + ||C||^2   (||f_hat||^2 = 1)
        lr[t] = 1.0f - 2.0f * v * g_cn1[i] + g_cn2[i];
    }
    __syncthreads();
    #pragma unroll
    for (int off = 64; off; off >>= 1) {
        if (t < off) lr[t] += lr[t + off];
        __syncthreads();
    }

    // ---- publish partial + last-CTA fused final reduce ----
    int* sflag = reinterpret_cast<int*>(smem_raw + 2560);
    if (t == 0) {
        g_partial[blockIdx.x] = lr[0];
        __threadfence();
        unsigned v = atomicAdd(&g_ticket, 1u);
        *sflag = (v == N_CTAS - 1);
    }
    __syncthreads();
    if (*sflag) {
        __threadfence();                        // acquire all partials
        float* sh = reinterpret_cast<float*>(smem_raw + 4096);
        float s = __ldcg(&g_partial[t])       + __ldcg(&g_partial[t + 256])
                + __ldcg(&g_partial[t + 512]) + __ldcg(&g_partial[t + 768]);
        sh[t] = s;
        __syncthreads();
        #pragma unroll
        for (int off = 128; off; off >>= 1) {
            if (t < off) sh[t] += sh[t + off];
            __syncthreads();
        }
        if (t == 0) {
            out[0] = sh[0] / (float)N_FEAT;
            g_ticket = 0;                       // reset for next graph replay
        }
    }
}

// ---------------- launch ----------------
extern "C" void kernel_launch(void* const* d_in, const int* in_sizes, int n_in,
                              void* d_out, int out_size) {
    const float* features = (const float*)d_in[0];
    const float* centers  = (const float*)d_in[1];
    if (n_in >= 2 && in_sizes[0] < in_sizes[1]) {   // defensive: order by size
        const float* tmp = features; features = centers; centers = tmp;
    }
    cudaFuncSetAttribute(cluster_main,
                         cudaFuncAttributeMaxDynamicSharedMemorySize, SMEM_BYTES);
    prep_centers<<<K_CENT / 8, 256>>>(centers);
    cluster_main<<<N_CTAS, 256, SMEM_BYTES>>>(features, (float*)d_out);
}